// round 12
// baseline (speedup 1.0000x reference)
#include <cuda_runtime.h>
#include <cuda_bf16.h>
#include <cuda_fp16.h>
#include <math.h>
#include <stdint.h>

#define BS 2
#define NQ 10000
#define NV 19560
#define EMBED 256
#define NHEAD 8
#define HDIM 32

typedef __nv_bfloat16 bf16;

// Scratch (allocation-free rule: __device__ globals)
__device__ __half g_vs[(size_t)BS * NV * EMBED];      // projected value fp16, row-major
__device__ float g_off[(size_t)BS * NQ * 256];
__device__ float g_attn[(size_t)BS * NQ * 128];

// bf16 hi/lo split operands
__device__ bf16 g_qh[(size_t)BS * NQ * 256];
__device__ bf16 g_ql[(size_t)BS * NQ * 256];
__device__ bf16 g_vh[(size_t)BS * NV * 256];
__device__ bf16 g_vl[(size_t)BS * NV * 256];
__device__ bf16 g_wvh[256 * 256], g_wvl[256 * 256];   // W_val^T  [n][k]
__device__ bf16 g_wqh[384 * 256], g_wql[384 * 256];   // [W_off^T ; W_attn^T]

// ===========================================================================
// helpers
// ===========================================================================
__device__ __forceinline__ uint32_t smem_u32(const void* p) {
    uint32_t a;
    asm("{ .reg .u64 t; cvta.to.shared.u64 t, %1; cvt.u32.u64 %0, t; }"
        : "=r"(a) : "l"(p));
    return a;
}
__device__ __forceinline__ void cvt_hl(float x, bf16& h, bf16& l) {
    h = __float2bfloat16_rn(x);
    l = __float2bfloat16_rn(x - __bfloat162float(h));
}

#define CP16(dst, src) \
    asm volatile("cp.async.cg.shared.global [%0], [%1], 16;" \
                 :: "r"(dst), "l"(src))
#define CP_COMMIT() asm volatile("cp.async.commit_group;")
#define CP_WAIT(n)  asm volatile("cp.async.wait_group %0;" :: "n"(n))

#define LDSM_X4(r0, r1, r2, r3, addr) \
    asm volatile("ldmatrix.sync.aligned.m8n8.x4.shared.b16 {%0,%1,%2,%3}, [%4];" \
                 : "=r"(r0), "=r"(r1), "=r"(r2), "=r"(r3) : "r"(addr))

__device__ __forceinline__ void mma_bf16(float* c,
                                         uint32_t a0, uint32_t a1, uint32_t a2, uint32_t a3,
                                         uint32_t b0, uint32_t b1) {
    asm volatile(
        "mma.sync.aligned.m16n8k16.row.col.f32.bf16.bf16.f32 "
        "{%0,%1,%2,%3}, {%4,%5,%6,%7}, {%8,%9}, {%0,%1,%2,%3};"
        : "+f"(c[0]), "+f"(c[1]), "+f"(c[2]), "+f"(c[3])
        : "r"(a0), "r"(a1), "r"(a2), "r"(a3), "r"(b0), "r"(b1));
}

// ===========================================================================
// conversion kernels
// ===========================================================================
// Merged: i < n4v -> value (no second addend); else query + qpos.
__global__ void conv_pair_all(const float* __restrict__ value,
                              const float* __restrict__ query,
                              const float* __restrict__ qpos,
                              bf16* __restrict__ vhi, bf16* __restrict__ vlo,
                              bf16* __restrict__ qhi, bf16* __restrict__ qlo,
                              int n4v, int n4tot)
{
    const int i = blockIdx.x * blockDim.x + threadIdx.x;
    if (i >= n4tot) return;
    float4 v;
    bf16 *hi, *lo;
    int j;
    if (i < n4v) {
        v = ((const float4*)value)[i];
        hi = vhi; lo = vlo; j = i;
    } else {
        j = i - n4v;
        v = ((const float4*)query)[j];
        float4 u = ((const float4*)qpos)[j];
        v.x += u.x; v.y += u.y; v.z += u.z; v.w += u.w;
        hi = qhi; lo = qlo;
    }
    bf16 h[4], l[4];
    cvt_hl(v.x, h[0], l[0]); cvt_hl(v.y, h[1], l[1]);
    cvt_hl(v.z, h[2], l[2]); cvt_hl(v.w, h[3], l[3]);
    ((uint2*)hi)[j] = *(uint2*)h;
    ((uint2*)lo)[j] = *(uint2*)l;
}

// Weights transposed in one launch; W_off and W_attn concatenated row-wise.
__global__ void conv_w_t_all(const float* __restrict__ Wv,
                             const float* __restrict__ Wo,
                             const float* __restrict__ Wa,
                             bf16* __restrict__ vh, bf16* __restrict__ vl,
                             bf16* __restrict__ qh2, bf16* __restrict__ ql2)
{
    const float* W;
    bf16 *th, *tl;
    int N;
    if (blockIdx.z == 0)      { W = Wv; th = vh;            tl = vl;            N = 256; }
    else if (blockIdx.z == 1) { W = Wo; th = qh2;           tl = ql2;           N = 256; }
    else                      { W = Wa; th = qh2 + 256*256; tl = ql2 + 256*256; N = 128; }
    if ((int)(blockIdx.x * 32) >= N) return;

    __shared__ float t[32][33];
    const int k0 = blockIdx.y * 32, n0 = blockIdx.x * 32;
    const int tx = threadIdx.x & 31, ty = threadIdx.x >> 5;
#pragma unroll
    for (int j = 0; j < 4; j++)
        t[ty + j * 8][tx] = W[(size_t)(k0 + ty + j * 8) * N + n0 + tx];
    __syncthreads();
#pragma unroll
    for (int j = 0; j < 4; j++) {
        const int n = n0 + ty + j * 8;
        const int k = k0 + tx;
        bf16 h, l;
        cvt_hl(t[tx][ty + j * 8], h, l);
        th[(size_t)n * 256 + k] = h;
        tl[(size_t)n * 256 + k] = l;
    }
}

// ===========================================================================
// bf16 3-term mma.sync GEMM with cp.async double buffering + ldmatrix.
// mode 1: fp16 row-major value output.  mode 2: split epilogue for off/attn.
// ===========================================================================
#define TSTR 40
#define TILE_B (128 * TSTR * 2)
#define BUF_B  (4 * TILE_B)
#define SMEM_TOT (2 * BUF_B)

__device__ __forceinline__ void load_chunk(uint32_t sb,
                                           const bf16* __restrict__ Ah_g,
                                           const bf16* __restrict__ Al_g,
                                           const bf16* __restrict__ Bh_g,
                                           const bf16* __restrict__ Bl_g,
                                           int m0, int n0, int M, int k0, int tid)
{
#pragma unroll
    for (int i = 0; i < 2; i++) {
        const int cid = tid + i * 256;
        const int row = cid >> 2;
        const int cp = cid & 3;
        int gm = m0 + row;
        if (gm >= M) gm = M - 1;
        const uint32_t doff = (uint32_t)(row * 80 + cp * 16);
        const size_t asrc = (size_t)gm * 256 + k0 + cp * 8;
        const size_t bsrc = (size_t)(n0 + row) * 256 + k0 + cp * 8;
        CP16(sb + doff,              Ah_g + asrc);
        CP16(sb + TILE_B + doff,     Al_g + asrc);
        CP16(sb + 2 * TILE_B + doff, Bh_g + bsrc);
        CP16(sb + 3 * TILE_B + doff, Bl_g + bsrc);
    }
}

__global__ __launch_bounds__(256)
void mma_gemm2(const bf16* __restrict__ Ah_g, const bf16* __restrict__ Al_g,
               const bf16* __restrict__ Bh_g, const bf16* __restrict__ Bl_g,
               const float* __restrict__ bias, const float* __restrict__ bias2,
               __half* __restrict__ Cv,
               float* __restrict__ C, float* __restrict__ C2,
               int M, int mode)
{
    extern __shared__ char smem[];
    const uint32_t sbase = smem_u32(smem);
    const int tid = threadIdx.x;
    const int wid = tid >> 5;
    const int lane = tid & 31;
    const int m0 = blockIdx.y * 128;
    const int n0 = blockIdx.x * 128;

    const int wm = wid >> 2;
    const int wn = wid & 3;
    const int grp = lane >> 2;
    const int qid = lane & 3;

    float acc[4][4][4];
#pragma unroll
    for (int i = 0; i < 4; i++)
#pragma unroll
        for (int j = 0; j < 4; j++)
#pragma unroll
            for (int r = 0; r < 4; r++) acc[i][j][r] = 0.f;

    const int mat = lane >> 3;
    const int arow_off = (lane & 7) + (mat & 1) * 8;
    const int akoff = (mat >> 1) * 16;
    const int brow_off = (lane & 7) + ((mat >> 1) & 1) * 8;
    const int bkoff = (mat & 1) * 16;

    load_chunk(sbase, Ah_g, Al_g, Bh_g, Bl_g, m0, n0, M, 0, tid);
    CP_COMMIT();

    const int NCH = 256 / 32;
#pragma unroll 1
    for (int c = 0; c < NCH; c++) {
        if (c + 1 < NCH) {
            load_chunk(sbase + ((c + 1) & 1) * BUF_B,
                       Ah_g, Al_g, Bh_g, Bl_g, m0, n0, M, (c + 1) * 32, tid);
            CP_COMMIT();
            CP_WAIT(1);
        } else {
            CP_WAIT(0);
        }
        __syncthreads();

        const uint32_t sA = sbase + (c & 1) * BUF_B;
        const uint32_t sAl = sA + TILE_B;
        const uint32_t sBh = sA + 2 * TILE_B;
        const uint32_t sBl = sA + 3 * TILE_B;

#pragma unroll
        for (int ks = 0; ks < 2; ks++) {
            const int kb = ks * 32;
            uint32_t ah[4][4], al[4][4], bh[4][2], bl[4][2];
#pragma unroll
            for (int tm = 0; tm < 4; tm++) {
                const uint32_t aaddr =
                    (uint32_t)((wm * 64 + tm * 16 + arow_off) * 80 + kb + akoff);
                LDSM_X4(ah[tm][0], ah[tm][1], ah[tm][2], ah[tm][3], sA + aaddr);
                LDSM_X4(al[tm][0], al[tm][1], al[tm][2], al[tm][3], sAl + aaddr);
            }
#pragma unroll
            for (int half = 0; half < 2; half++) {
                const uint32_t baddr =
                    (uint32_t)((wn * 32 + half * 16 + brow_off) * 80 + kb + bkoff);
                uint32_t t0, t1, t2, t3;
                LDSM_X4(t0, t1, t2, t3, sBh + baddr);
                bh[half * 2][0] = t0; bh[half * 2][1] = t1;
                bh[half * 2 + 1][0] = t2; bh[half * 2 + 1][1] = t3;
                LDSM_X4(t0, t1, t2, t3, sBl + baddr);
                bl[half * 2][0] = t0; bl[half * 2][1] = t1;
                bl[half * 2 + 1][0] = t2; bl[half * 2 + 1][1] = t3;
            }
#pragma unroll
            for (int tm = 0; tm < 4; tm++)
#pragma unroll
                for (int tn = 0; tn < 4; tn++) {
                    float* cc = acc[tm][tn];
                    mma_bf16(cc, ah[tm][0], ah[tm][1], ah[tm][2], ah[tm][3],
                             bh[tn][0], bh[tn][1]);
                    mma_bf16(cc, ah[tm][0], ah[tm][1], ah[tm][2], ah[tm][3],
                             bl[tn][0], bl[tn][1]);
                    mma_bf16(cc, al[tm][0], al[tm][1], al[tm][2], al[tm][3],
                             bh[tn][0], bh[tn][1]);
                }
        }
        __syncthreads();
    }

#pragma unroll
    for (int tm = 0; tm < 4; tm++) {
#pragma unroll
        for (int half = 0; half < 2; half++) {
            const int gm = m0 + wm * 64 + tm * 16 + grp + half * 8;
            if (gm >= M) continue;
#pragma unroll
            for (int tn = 0; tn < 4; tn++) {
                const int gn = n0 + wn * 32 + tn * 8 + qid * 2;
                float2 o;
                o.x = acc[tm][tn][half * 2 + 0];
                o.y = acc[tm][tn][half * 2 + 1];
                if (mode == 1) {
                    float2 bsv = *(const float2*)(bias + gn);
                    o.x += bsv.x; o.y += bsv.y;
                    __half2 hv = __floats2half2_rn(o.x, o.y);
                    *(__half2*)(Cv + (size_t)gm * 256 + gn) = hv;
                } else {
                    if (gn < 256) {
                        float2 bsv = *(const float2*)(bias + gn);
                        o.x += bsv.x; o.y += bsv.y;
                        *(float2*)(C + (size_t)gm * 256 + gn) = o;
                    } else {
                        float2 bsv = *(const float2*)(bias2 + gn - 256);
                        o.x += bsv.x; o.y += bsv.y;
                        *(float2*)(C2 + (size_t)gm * 128 + gn - 256) = o;
                    }
                }
            }
        }
    }
}

// ---------------------------------------------------------------------------
// Deformable sampling v6: one warp = one (b, q), all 8 heads, fp16 value in
// ROW-MAJOR layout. Each corner load is one fully contiguous 512B warp
// transaction (lane i loads emb channels [i*8, i*8+8) of value[pos]) — 4
// L1tex wavefronts per corner instead of 8 with the per-head-plane layout.
// lane -> (h = lane>>2, pt = lane&3) for softmax/coords, matching the
// channel ownership exactly.
// ---------------------------------------------------------------------------
__global__ void sample_kernel(const float* __restrict__ refpts,
                              float* __restrict__ out)
{
    const int gwarp = (blockIdx.x * blockDim.x + threadIdx.x) >> 5;
    const int lane = threadIdx.x & 31;
    if (gwarp >= BS * NQ) return;

    const int bq = gwarp;
    const int b  = bq / NQ;
    const int h  = lane >> 2;
    const int pt = lane & 3;
    const unsigned FULL = 0xFFFFFFFFu;

    float a[4];
#pragma unroll
    for (int lv = 0; lv < 4; lv++)
        a[lv] = g_attn[(size_t)bq * 128 + h * 16 + lv * 4 + pt];

    float amax = fmaxf(fmaxf(a[0], a[1]), fmaxf(a[2], a[3]));
    amax = fmaxf(amax, __shfl_xor_sync(FULL, amax, 1));
    amax = fmaxf(amax, __shfl_xor_sync(FULL, amax, 2));
    float wgt[4];
    float es = 0.f;
#pragma unroll
    for (int lv = 0; lv < 4; lv++) { wgt[lv] = __expf(a[lv] - amax); es += wgt[lv]; }
    es += __shfl_xor_sync(FULL, es, 1);
    es += __shfl_xor_sync(FULL, es, 2);
    const float inv = 1.f / es;
#pragma unroll
    for (int lv = 0; lv < 4; lv++) wgt[lv] *= inv;

    const float LW[4] = {160.f, 80.f, 40.f, 20.f};
    const float LH[4] = {92.f, 46.f, 23.f, 12.f};
    const float rx = refpts[(size_t)bq * 8 + pt * 2 + 0];
    const float ry = refpts[(size_t)bq * 8 + pt * 2 + 1];
    float x[4], y[4];
#pragma unroll
    for (int lv = 0; lv < 4; lv++) {
        const float offx = g_off[(size_t)bq * 256 + h * 32 + lv * 8 + pt * 2 + 0];
        const float offy = g_off[(size_t)bq * 256 + h * 32 + lv * 8 + pt * 2 + 1];
        x[lv] = fmaf(rx + offx / LW[lv], LW[lv], -0.5f);
        y[lv] = fmaf(ry + offy / LH[lv], LH[lv], -0.5f);
    }

    const int HH[4] = {92, 46, 23, 12};
    const int WW[4] = {160, 80, 40, 20};
    const int ST[4] = {0, 14720, 18400, 19320};

    // row-major fp16 value: one position = 512B = 32 uint4; lane takes uint4 #lane
    const uint4* __restrict__ vp =
        (const uint4*)(g_vs + (size_t)b * NV * EMBED) + lane;

    float2 a0 = {0.f, 0.f}, a1 = {0.f, 0.f}, a2 = {0.f, 0.f}, a3 = {0.f, 0.f};
    const int src_base = lane & 28;

#pragma unroll
    for (int p = 0; p < 16; p++) {
        const int lv = p >> 2;
        const int pp = p & 3;
        const int src = src_base | pp;
        const float xp = __shfl_sync(FULL, x[lv], src);
        const float yp = __shfl_sync(FULL, y[lv], src);
        const float wp = __shfl_sync(FULL, wgt[lv], src);
        const int Hl = HH[lv], Wl = WW[lv], base = ST[lv];

        const float x0f = floorf(xp), y0f = floorf(yp);
        const float wx1r = xp - x0f;
        const float wy1r = yp - y0f;
        const int x0 = (int)x0f, y0 = (int)y0f;

        const bool vx0 = (unsigned)x0 < (unsigned)Wl;
        const bool vx1 = (unsigned)(x0 + 1) < (unsigned)Wl;
        const bool vy0 = (unsigned)y0 < (unsigned)Hl;
        const bool vy1 = (unsigned)(y0 + 1) < (unsigned)Hl;

        const float wy0 = vy0 ? (1.f - wy1r) * wp : 0.f;
        const float wy1 = vy1 ? wy1r * wp : 0.f;
        const float wxa = vx0 ? (1.f - wx1r) : 0.f;
        const float wxb = vx1 ? wx1r : 0.f;

        const int x0c = min(max(x0, 0), Wl - 1);
        const int x1c = min(max(x0 + 1, 0), Wl - 1);
        const int y0c = min(max(y0, 0), Hl - 1);
        const int y1c = min(max(y0 + 1, 0), Hl - 1);

        const int r0 = (base + y0c * Wl) * 32;   // uint4 units per position = 32
        const int r1 = (base + y1c * Wl) * 32;

#pragma unroll
        for (int cn = 0; cn < 4; cn++) {
            const int idx = (cn < 2 ? r0 : r1) + ((cn & 1) ? x1c : x0c) * 32;
            const float cw = (cn == 0 ? wy0 * wxa : cn == 1 ? wy0 * wxb
                              : cn == 2 ? wy1 * wxa : wy1 * wxb);
            const uint4 u = __ldg(vp + idx);
            const float2 f0 = __half22float2(*(const __half2*)&u.x);
            const float2 f1 = __half22float2(*(const __half2*)&u.y);
            const float2 f2 = __half22float2(*(const __half2*)&u.z);
            const float2 f3 = __half22float2(*(const __half2*)&u.w);
            a0.x = fmaf(f0.x, cw, a0.x); a0.y = fmaf(f0.y, cw, a0.y);
            a1.x = fmaf(f1.x, cw, a1.x); a1.y = fmaf(f1.y, cw, a1.y);
            a2.x = fmaf(f2.x, cw, a2.x); a2.y = fmaf(f2.y, cw, a2.y);
            a3.x = fmaf(f3.x, cw, a3.x); a3.y = fmaf(f3.y, cw, a3.y);
        }
    }

    // lane's channels are emb [lane*8, lane*8+8) = out + lane*8
    float* op = out + (size_t)bq * EMBED + lane * 8;
    *(float4*)(op)     = make_float4(a0.x, a0.y, a1.x, a1.y);
    *(float4*)(op + 4) = make_float4(a2.x, a2.y, a3.x, a3.y);
}

// ---------------------------------------------------------------------------
extern "C" void kernel_launch(void* const* d_in, const int* in_sizes, int n_in,
                              void* d_out, int out_size)
{
    const float* query   = (const float*)d_in[0];
    const float* value   = (const float*)d_in[1];
    const float* qpos    = (const float*)d_in[2];
    const float* refpts  = (const float*)d_in[3];
    const float* W_val   = (const float*)d_in[4];
    const float* b_val   = (const float*)d_in[5];
    const float* W_off   = (const float*)d_in[6];
    const float* b_off   = (const float*)d_in[7];
    const float* W_attn  = (const float*)d_in[8];
    const float* b_attn  = (const float*)d_in[9];
    float* out = (float*)d_out;

    __half* pvs;
    float *poff, *pattn;
    cudaGetSymbolAddress((void**)&pvs, g_vs);
    cudaGetSymbolAddress((void**)&poff, g_off);
    cudaGetSymbolAddress((void**)&pattn, g_attn);

    bf16 *qh, *ql, *vh, *vl, *wvh, *wvl, *wqh, *wql;
    cudaGetSymbolAddress((void**)&qh, g_qh);
    cudaGetSymbolAddress((void**)&ql, g_ql);
    cudaGetSymbolAddress((void**)&vh, g_vh);
    cudaGetSymbolAddress((void**)&vl, g_vl);
    cudaGetSymbolAddress((void**)&wvh, g_wvh);
    cudaGetSymbolAddress((void**)&wvl, g_wvl);
    cudaGetSymbolAddress((void**)&wqh, g_wqh);
    cudaGetSymbolAddress((void**)&wql, g_wql);

    const int Mv = BS * NV;      // 39120
    const int Mq = BS * NQ;      // 20000

    cudaFuncSetAttribute(mma_gemm2, cudaFuncAttributeMaxDynamicSharedMemorySize,
                         SMEM_TOT);

    // conversions (merged elementwise launch + weight transpose launch)
    {
        const int n4v = Mv * 256 / 4;
        const int n4q = Mq * 256 / 4;
        const int n4tot = n4v + n4q;
        conv_pair_all<<<(n4tot + 255) / 256, 256>>>(value, query, qpos,
                                                    vh, vl, qh, ql, n4v, n4tot);
    }
    conv_w_t_all<<<dim3(8, 8, 3), 256>>>(W_val, W_off, W_attn,
                                         wvh, wvl, wqh, wql);

    // value projection -> fp16 row-major
    mma_gemm2<<<dim3(2, (Mv + 127) / 128), 256, SMEM_TOT>>>(
        vh, vl, wvh, wvl, b_val, nullptr, pvs, nullptr, nullptr, Mv, 1);
    // merged offsets + attn logits: N = 384
    mma_gemm2<<<dim3(3, (Mq + 127) / 128), 256, SMEM_TOT>>>(
        qh, ql, wqh, wql, b_off, b_attn, nullptr, poff, pattn, Mq, 2);

    // sampling + weighted sum (one warp per (b,q))
    {
        const int total_warps = BS * NQ;                 // 20000
        const int warps_per_block = 8;
        const int blocks = (total_warps + warps_per_block - 1) / warps_per_block;
        sample_kernel<<<blocks, warps_per_block * 32>>>(refpts, out);
    }
}

// round 13
// speedup vs baseline: 1.4391x; 1.4391x over previous
#include <cuda_runtime.h>
#include <cuda_bf16.h>
#include <cuda_fp16.h>
#include <math.h>
#include <stdint.h>

#define BS 2
#define NQ 10000
#define NV 19560
#define EMBED 256
#define NHEAD 8
#define HDIM 32
#define VSTR 320   // padded halfs per position (640 B: toggles hashed bit 8)

typedef __nv_bfloat16 bf16;

// Scratch (allocation-free rule: __device__ globals)
__device__ __half g_vs[(size_t)BS * NV * VSTR];       // projected value fp16, padded row-major
__device__ float g_off[(size_t)BS * NQ * 256];
__device__ float g_attn[(size_t)BS * NQ * 128];

// bf16 hi/lo split operands
__device__ bf16 g_qh[(size_t)BS * NQ * 256];
__device__ bf16 g_ql[(size_t)BS * NQ * 256];
__device__ bf16 g_vh[(size_t)BS * NV * 256];
__device__ bf16 g_vl[(size_t)BS * NV * 256];
__device__ bf16 g_wvh[256 * 256], g_wvl[256 * 256];   // W_val^T  [n][k]
__device__ bf16 g_wqh[384 * 256], g_wql[384 * 256];   // [W_off^T ; W_attn^T]

// ===========================================================================
// helpers
// ===========================================================================
__device__ __forceinline__ uint32_t smem_u32(const void* p) {
    uint32_t a;
    asm("{ .reg .u64 t; cvta.to.shared.u64 t, %1; cvt.u32.u64 %0, t; }"
        : "=r"(a) : "l"(p));
    return a;
}
__device__ __forceinline__ void cvt_hl(float x, bf16& h, bf16& l) {
    h = __float2bfloat16_rn(x);
    l = __float2bfloat16_rn(x - __bfloat162float(h));
}

#define CP16(dst, src) \
    asm volatile("cp.async.cg.shared.global [%0], [%1], 16;" \
                 :: "r"(dst), "l"(src))
#define CP_COMMIT() asm volatile("cp.async.commit_group;")
#define CP_WAIT(n)  asm volatile("cp.async.wait_group %0;" :: "n"(n))

#define LDSM_X4(r0, r1, r2, r3, addr) \
    asm volatile("ldmatrix.sync.aligned.m8n8.x4.shared.b16 {%0,%1,%2,%3}, [%4];" \
                 : "=r"(r0), "=r"(r1), "=r"(r2), "=r"(r3) : "r"(addr))

__device__ __forceinline__ void mma_bf16(float* c,
                                         uint32_t a0, uint32_t a1, uint32_t a2, uint32_t a3,
                                         uint32_t b0, uint32_t b1) {
    asm volatile(
        "mma.sync.aligned.m16n8k16.row.col.f32.bf16.bf16.f32 "
        "{%0,%1,%2,%3}, {%4,%5,%6,%7}, {%8,%9}, {%0,%1,%2,%3};"
        : "+f"(c[0]), "+f"(c[1]), "+f"(c[2]), "+f"(c[3])
        : "r"(a0), "r"(a1), "r"(a2), "r"(a3), "r"(b0), "r"(b1));
}

// ===========================================================================
// conversion kernels (exact round-11 versions)
// ===========================================================================
__global__ void conv_pair(const float* __restrict__ x, const float* __restrict__ x2,
                          bf16* __restrict__ hi, bf16* __restrict__ lo, int n4)
{
    const int i = blockIdx.x * blockDim.x + threadIdx.x;
    if (i >= n4) return;
    float4 v = ((const float4*)x)[i];
    if (x2) {
        float4 u = ((const float4*)x2)[i];
        v.x += u.x; v.y += u.y; v.z += u.z; v.w += u.w;
    }
    bf16 h[4], l[4];
    cvt_hl(v.x, h[0], l[0]); cvt_hl(v.y, h[1], l[1]);
    cvt_hl(v.z, h[2], l[2]); cvt_hl(v.w, h[3], l[3]);
    ((uint2*)hi)[i] = *(uint2*)h;
    ((uint2*)lo)[i] = *(uint2*)l;
}

__global__ void conv_w_t_all(const float* __restrict__ Wv,
                             const float* __restrict__ Wo,
                             const float* __restrict__ Wa,
                             bf16* __restrict__ vh, bf16* __restrict__ vl,
                             bf16* __restrict__ qh2, bf16* __restrict__ ql2)
{
    const float* W;
    bf16 *th, *tl;
    int N;
    if (blockIdx.z == 0)      { W = Wv; th = vh;            tl = vl;            N = 256; }
    else if (blockIdx.z == 1) { W = Wo; th = qh2;           tl = ql2;           N = 256; }
    else                      { W = Wa; th = qh2 + 256*256; tl = ql2 + 256*256; N = 128; }
    if ((int)(blockIdx.x * 32) >= N) return;

    __shared__ float t[32][33];
    const int k0 = blockIdx.y * 32, n0 = blockIdx.x * 32;
    const int tx = threadIdx.x & 31, ty = threadIdx.x >> 5;
#pragma unroll
    for (int j = 0; j < 4; j++)
        t[ty + j * 8][tx] = W[(size_t)(k0 + ty + j * 8) * N + n0 + tx];
    __syncthreads();
#pragma unroll
    for (int j = 0; j < 4; j++) {
        const int n = n0 + ty + j * 8;
        const int k = k0 + tx;
        bf16 h, l;
        cvt_hl(t[tx][ty + j * 8], h, l);
        th[(size_t)n * 256 + k] = h;
        tl[(size_t)n * 256 + k] = l;
    }
}

// ===========================================================================
// bf16 3-term mma.sync GEMM with cp.async double buffering + ldmatrix.
// mode 1: fp16 padded-row-major value output (stride VSTR).
// mode 2: split epilogue for off/attn.
// ===========================================================================
#define TSTR 40
#define TILE_B (128 * TSTR * 2)
#define BUF_B  (4 * TILE_B)
#define SMEM_TOT (2 * BUF_B)

__device__ __forceinline__ void load_chunk(uint32_t sb,
                                           const bf16* __restrict__ Ah_g,
                                           const bf16* __restrict__ Al_g,
                                           const bf16* __restrict__ Bh_g,
                                           const bf16* __restrict__ Bl_g,
                                           int m0, int n0, int M, int k0, int tid)
{
#pragma unroll
    for (int i = 0; i < 2; i++) {
        const int cid = tid + i * 256;
        const int row = cid >> 2;
        const int cp = cid & 3;
        int gm = m0 + row;
        if (gm >= M) gm = M - 1;
        const uint32_t doff = (uint32_t)(row * 80 + cp * 16);
        const size_t asrc = (size_t)gm * 256 + k0 + cp * 8;
        const size_t bsrc = (size_t)(n0 + row) * 256 + k0 + cp * 8;
        CP16(sb + doff,              Ah_g + asrc);
        CP16(sb + TILE_B + doff,     Al_g + asrc);
        CP16(sb + 2 * TILE_B + doff, Bh_g + bsrc);
        CP16(sb + 3 * TILE_B + doff, Bl_g + bsrc);
    }
}

__global__ __launch_bounds__(256)
void mma_gemm2(const bf16* __restrict__ Ah_g, const bf16* __restrict__ Al_g,
               const bf16* __restrict__ Bh_g, const bf16* __restrict__ Bl_g,
               const float* __restrict__ bias, const float* __restrict__ bias2,
               __half* __restrict__ Cv,
               float* __restrict__ C, float* __restrict__ C2,
               int M, int mode)
{
    extern __shared__ char smem[];
    const uint32_t sbase = smem_u32(smem);
    const int tid = threadIdx.x;
    const int wid = tid >> 5;
    const int lane = tid & 31;
    const int m0 = blockIdx.y * 128;
    const int n0 = blockIdx.x * 128;

    const int wm = wid >> 2;
    const int wn = wid & 3;
    const int grp = lane >> 2;
    const int qid = lane & 3;

    float acc[4][4][4];
#pragma unroll
    for (int i = 0; i < 4; i++)
#pragma unroll
        for (int j = 0; j < 4; j++)
#pragma unroll
            for (int r = 0; r < 4; r++) acc[i][j][r] = 0.f;

    const int mat = lane >> 3;
    const int arow_off = (lane & 7) + (mat & 1) * 8;
    const int akoff = (mat >> 1) * 16;
    const int brow_off = (lane & 7) + ((mat >> 1) & 1) * 8;
    const int bkoff = (mat & 1) * 16;

    load_chunk(sbase, Ah_g, Al_g, Bh_g, Bl_g, m0, n0, M, 0, tid);
    CP_COMMIT();

    const int NCH = 256 / 32;
#pragma unroll 1
    for (int c = 0; c < NCH; c++) {
        if (c + 1 < NCH) {
            load_chunk(sbase + ((c + 1) & 1) * BUF_B,
                       Ah_g, Al_g, Bh_g, Bl_g, m0, n0, M, (c + 1) * 32, tid);
            CP_COMMIT();
            CP_WAIT(1);
        } else {
            CP_WAIT(0);
        }
        __syncthreads();

        const uint32_t sA = sbase + (c & 1) * BUF_B;
        const uint32_t sAl = sA + TILE_B;
        const uint32_t sBh = sA + 2 * TILE_B;
        const uint32_t sBl = sA + 3 * TILE_B;

#pragma unroll
        for (int ks = 0; ks < 2; ks++) {
            const int kb = ks * 32;
            uint32_t ah[4][4], al[4][4], bh[4][2], bl[4][2];
#pragma unroll
            for (int tm = 0; tm < 4; tm++) {
                const uint32_t aaddr =
                    (uint32_t)((wm * 64 + tm * 16 + arow_off) * 80 + kb + akoff);
                LDSM_X4(ah[tm][0], ah[tm][1], ah[tm][2], ah[tm][3], sA + aaddr);
                LDSM_X4(al[tm][0], al[tm][1], al[tm][2], al[tm][3], sAl + aaddr);
            }
#pragma unroll
            for (int half = 0; half < 2; half++) {
                const uint32_t baddr =
                    (uint32_t)((wn * 32 + half * 16 + brow_off) * 80 + kb + bkoff);
                uint32_t t0, t1, t2, t3;
                LDSM_X4(t0, t1, t2, t3, sBh + baddr);
                bh[half * 2][0] = t0; bh[half * 2][1] = t1;
                bh[half * 2 + 1][0] = t2; bh[half * 2 + 1][1] = t3;
                LDSM_X4(t0, t1, t2, t3, sBl + baddr);
                bl[half * 2][0] = t0; bl[half * 2][1] = t1;
                bl[half * 2 + 1][0] = t2; bl[half * 2 + 1][1] = t3;
            }
#pragma unroll
            for (int tm = 0; tm < 4; tm++)
#pragma unroll
                for (int tn = 0; tn < 4; tn++) {
                    float* cc = acc[tm][tn];
                    mma_bf16(cc, ah[tm][0], ah[tm][1], ah[tm][2], ah[tm][3],
                             bh[tn][0], bh[tn][1]);
                    mma_bf16(cc, ah[tm][0], ah[tm][1], ah[tm][2], ah[tm][3],
                             bl[tn][0], bl[tn][1]);
                    mma_bf16(cc, al[tm][0], al[tm][1], al[tm][2], al[tm][3],
                             bh[tn][0], bh[tn][1]);
                }
        }
        __syncthreads();
    }

#pragma unroll
    for (int tm = 0; tm < 4; tm++) {
#pragma unroll
        for (int half = 0; half < 2; half++) {
            const int gm = m0 + wm * 64 + tm * 16 + grp + half * 8;
            if (gm >= M) continue;
#pragma unroll
            for (int tn = 0; tn < 4; tn++) {
                const int gn = n0 + wn * 32 + tn * 8 + qid * 2;
                float2 o;
                o.x = acc[tm][tn][half * 2 + 0];
                o.y = acc[tm][tn][half * 2 + 1];
                if (mode == 1) {
                    float2 bsv = *(const float2*)(bias + gn);
                    o.x += bsv.x; o.y += bsv.y;
                    __half2 hv = __floats2half2_rn(o.x, o.y);
                    *(__half2*)(Cv + (size_t)gm * VSTR + gn) = hv;
                } else {
                    if (gn < 256) {
                        float2 bsv = *(const float2*)(bias + gn);
                        o.x += bsv.x; o.y += bsv.y;
                        *(float2*)(C + (size_t)gm * 256 + gn) = o;
                    } else {
                        float2 bsv = *(const float2*)(bias2 + gn - 256);
                        o.x += bsv.x; o.y += bsv.y;
                        *(float2*)(C2 + (size_t)gm * 128 + gn - 256) = o;
                    }
                }
            }
        }
    }
}

// ---------------------------------------------------------------------------
// Deformable sampling v7: one warp = one (b, q), all 8 heads, fp16 value in
// PADDED row-major layout (VSTR=320 halfs = 640 B per position). Each corner
// load is one 512 B contiguous warp transaction = 4 L1tex wavefronts, and the
// 640 B position stride toggles hashed address bit 8 -> full LTS slice spread
// (the 512 B stride of v6 kept bit 8 constant and pair-collided on slices).
// ---------------------------------------------------------------------------
__global__ void sample_kernel(const float* __restrict__ refpts,
                              float* __restrict__ out)
{
    const int gwarp = (blockIdx.x * blockDim.x + threadIdx.x) >> 5;
    const int lane = threadIdx.x & 31;
    if (gwarp >= BS * NQ) return;

    const int bq = gwarp;
    const int b  = bq / NQ;
    const int h  = lane >> 2;
    const int pt = lane & 3;
    const unsigned FULL = 0xFFFFFFFFu;

    float a[4];
#pragma unroll
    for (int lv = 0; lv < 4; lv++)
        a[lv] = g_attn[(size_t)bq * 128 + h * 16 + lv * 4 + pt];

    float amax = fmaxf(fmaxf(a[0], a[1]), fmaxf(a[2], a[3]));
    amax = fmaxf(amax, __shfl_xor_sync(FULL, amax, 1));
    amax = fmaxf(amax, __shfl_xor_sync(FULL, amax, 2));
    float wgt[4];
    float es = 0.f;
#pragma unroll
    for (int lv = 0; lv < 4; lv++) { wgt[lv] = __expf(a[lv] - amax); es += wgt[lv]; }
    es += __shfl_xor_sync(FULL, es, 1);
    es += __shfl_xor_sync(FULL, es, 2);
    const float inv = 1.f / es;
#pragma unroll
    for (int lv = 0; lv < 4; lv++) wgt[lv] *= inv;

    const float LW[4] = {160.f, 80.f, 40.f, 20.f};
    const float LH[4] = {92.f, 46.f, 23.f, 12.f};
    const float rx = refpts[(size_t)bq * 8 + pt * 2 + 0];
    const float ry = refpts[(size_t)bq * 8 + pt * 2 + 1];
    float x[4], y[4];
#pragma unroll
    for (int lv = 0; lv < 4; lv++) {
        const float offx = g_off[(size_t)bq * 256 + h * 32 + lv * 8 + pt * 2 + 0];
        const float offy = g_off[(size_t)bq * 256 + h * 32 + lv * 8 + pt * 2 + 1];
        x[lv] = fmaf(rx + offx / LW[lv], LW[lv], -0.5f);
        y[lv] = fmaf(ry + offy / LH[lv], LH[lv], -0.5f);
    }

    const int HH[4] = {92, 46, 23, 12};
    const int WW[4] = {160, 80, 40, 20};
    const int ST[4] = {0, 14720, 18400, 19320};

    // padded row-major fp16 value: 40 uint4 per position; lane takes uint4 #lane
    const uint4* __restrict__ vp =
        (const uint4*)g_vs + (size_t)b * NV * (VSTR / 8) + lane;

    float2 a0 = {0.f, 0.f}, a1 = {0.f, 0.f}, a2 = {0.f, 0.f}, a3 = {0.f, 0.f};
    const int src_base = lane & 28;

#pragma unroll
    for (int p = 0; p < 16; p++) {
        const int lv = p >> 2;
        const int pp = p & 3;
        const int src = src_base | pp;
        const float xp = __shfl_sync(FULL, x[lv], src);
        const float yp = __shfl_sync(FULL, y[lv], src);
        const float wp = __shfl_sync(FULL, wgt[lv], src);
        const int Hl = HH[lv], Wl = WW[lv], base = ST[lv];

        const float x0f = floorf(xp), y0f = floorf(yp);
        const float wx1r = xp - x0f;
        const float wy1r = yp - y0f;
        const int x0 = (int)x0f, y0 = (int)y0f;

        const bool vx0 = (unsigned)x0 < (unsigned)Wl;
        const bool vx1 = (unsigned)(x0 + 1) < (unsigned)Wl;
        const bool vy0 = (unsigned)y0 < (unsigned)Hl;
        const bool vy1 = (unsigned)(y0 + 1) < (unsigned)Hl;

        const float wy0 = vy0 ? (1.f - wy1r) * wp : 0.f;
        const float wy1 = vy1 ? wy1r * wp : 0.f;
        const float wxa = vx0 ? (1.f - wx1r) : 0.f;
        const float wxb = vx1 ? wx1r : 0.f;

        const int x0c = min(max(x0, 0), Wl - 1);
        const int x1c = min(max(x0 + 1, 0), Wl - 1);
        const int y0c = min(max(y0, 0), Hl - 1);
        const int y1c = min(max(y0 + 1, 0), Hl - 1);

        const int r0 = (base + y0c * Wl) * (VSTR / 8);
        const int r1 = (base + y1c * Wl) * (VSTR / 8);

#pragma unroll
        for (int cn = 0; cn < 4; cn++) {
            const int idx = (cn < 2 ? r0 : r1) + ((cn & 1) ? x1c : x0c) * (VSTR / 8);
            const float cw = (cn == 0 ? wy0 * wxa : cn == 1 ? wy0 * wxb
                              : cn == 2 ? wy1 * wxa : wy1 * wxb);
            const uint4 u = __ldg(vp + idx);
            const float2 f0 = __half22float2(*(const __half2*)&u.x);
            const float2 f1 = __half22float2(*(const __half2*)&u.y);
            const float2 f2 = __half22float2(*(const __half2*)&u.z);
            const float2 f3 = __half22float2(*(const __half2*)&u.w);
            a0.x = fmaf(f0.x, cw, a0.x); a0.y = fmaf(f0.y, cw, a0.y);
            a1.x = fmaf(f1.x, cw, a1.x); a1.y = fmaf(f1.y, cw, a1.y);
            a2.x = fmaf(f2.x, cw, a2.x); a2.y = fmaf(f2.y, cw, a2.y);
            a3.x = fmaf(f3.x, cw, a3.x); a3.y = fmaf(f3.y, cw, a3.y);
        }
    }

    // lane's channels are emb [lane*8, lane*8+8)
    float* op = out + (size_t)bq * EMBED + lane * 8;
    *(float4*)(op)     = make_float4(a0.x, a0.y, a1.x, a1.y);
    *(float4*)(op + 4) = make_float4(a2.x, a2.y, a3.x, a3.y);
}

// ---------------------------------------------------------------------------
extern "C" void kernel_launch(void* const* d_in, const int* in_sizes, int n_in,
                              void* d_out, int out_size)
{
    const float* query   = (const float*)d_in[0];
    const float* value   = (const float*)d_in[1];
    const float* qpos    = (const float*)d_in[2];
    const float* refpts  = (const float*)d_in[3];
    const float* W_val   = (const float*)d_in[4];
    const float* b_val   = (const float*)d_in[5];
    const float* W_off   = (const float*)d_in[6];
    const float* b_off   = (const float*)d_in[7];
    const float* W_attn  = (const float*)d_in[8];
    const float* b_attn  = (const float*)d_in[9];
    float* out = (float*)d_out;

    __half* pvs;
    float *poff, *pattn;
    cudaGetSymbolAddress((void**)&pvs, g_vs);
    cudaGetSymbolAddress((void**)&poff, g_off);
    cudaGetSymbolAddress((void**)&pattn, g_attn);

    bf16 *qh, *ql, *vh, *vl, *wvh, *wvl, *wqh, *wql;
    cudaGetSymbolAddress((void**)&qh, g_qh);
    cudaGetSymbolAddress((void**)&ql, g_ql);
    cudaGetSymbolAddress((void**)&vh, g_vh);
    cudaGetSymbolAddress((void**)&vl, g_vl);
    cudaGetSymbolAddress((void**)&wvh, g_wvh);
    cudaGetSymbolAddress((void**)&wvl, g_wvl);
    cudaGetSymbolAddress((void**)&wqh, g_wqh);
    cudaGetSymbolAddress((void**)&wql, g_wql);

    const int Mv = BS * NV;      // 39120
    const int Mq = BS * NQ;      // 20000

    cudaFuncSetAttribute(mma_gemm2, cudaFuncAttributeMaxDynamicSharedMemorySize,
                         SMEM_TOT);

    // conversions (exact round-11 structure)
    {
        int n4 = Mv * 256 / 4;
        conv_pair<<<(n4 + 255) / 256, 256>>>(value, nullptr, vh, vl, n4);
    }
    {
        int n4 = Mq * 256 / 4;
        conv_pair<<<(n4 + 255) / 256, 256>>>(query, qpos, qh, ql, n4);
    }
    conv_w_t_all<<<dim3(8, 8, 3), 256>>>(W_val, W_off, W_attn,
                                         wvh, wvl, wqh, wql);

    // value projection -> fp16 padded row-major
    mma_gemm2<<<dim3(2, (Mv + 127) / 128), 256, SMEM_TOT>>>(
        vh, vl, wvh, wvl, b_val, nullptr, pvs, nullptr, nullptr, Mv, 1);
    // merged offsets + attn logits: N = 384
    mma_gemm2<<<dim3(3, (Mq + 127) / 128), 256, SMEM_TOT>>>(
        qh, ql, wqh, wql, b_off, b_attn, nullptr, poff, pattn, Mq, 2);

    // sampling + weighted sum (one warp per (b,q))
    {
        const int total_warps = BS * NQ;                 // 20000
        const int warps_per_block = 8;
        const int blocks = (total_warps + warps_per_block - 1) / warps_per_block;
        sample_kernel<<<blocks, warps_per_block * 32>>>(refpts, out);
    }
}

// round 14
// speedup vs baseline: 1.7033x; 1.1835x over previous
#include <cuda_runtime.h>
#include <cuda_fp16.h>
#include <math.h>
#include <stdint.h>

#define BS 2
#define NQ 10000
#define NV 19560
#define EMBED 256
#define NHEAD 8
#define HDIM 32
#define VSTR 320   // padded halfs per position (640 B: toggles hashed bit 8)

// Scratch (allocation-free rule: __device__ globals)
__device__ __half g_vs[(size_t)BS * NV * VSTR];   // projected value fp16, padded row-major
__device__ float g_off[(size_t)BS * NQ * 256];
__device__ float g_attn[(size_t)BS * NQ * 128];
__device__ float g_q[(size_t)BS * NQ * 256];      // query + qpos
__device__ float g_wvt[256 * 256];                // W_val^T  [n][k]
__device__ float g_wqt[384 * 256];                // [W_off^T ; W_attn^T]

// ===========================================================================
// helpers
// ===========================================================================
__device__ __forceinline__ uint32_t smem_u32(const void* p) {
    uint32_t a;
    asm("{ .reg .u64 t; cvta.to.shared.u64 t, %1; cvt.u32.u64 %0, t; }"
        : "=r"(a) : "l"(p));
    return a;
}
__device__ __forceinline__ uint32_t f2tf(float f) {
    uint32_t r;
    asm("cvt.rna.tf32.f32 %0, %1;" : "=r"(r) : "f"(f));
    return r;
}

#define CP16(dst, src) \
    asm volatile("cp.async.cg.shared.global [%0], [%1], 16;" \
                 :: "r"(dst), "l"(src))
#define CP_COMMIT() asm volatile("cp.async.commit_group;")
#define CP_WAIT(n)  asm volatile("cp.async.wait_group %0;" :: "n"(n))

__device__ __forceinline__ void mma_tf32(float* c,
                                         uint32_t a0, uint32_t a1, uint32_t a2, uint32_t a3,
                                         uint32_t b0, uint32_t b1) {
    asm volatile(
        "mma.sync.aligned.m16n8k8.row.col.f32.tf32.tf32.f32 "
        "{%0,%1,%2,%3}, {%4,%5,%6,%7}, {%8,%9}, {%0,%1,%2,%3};"
        : "+f"(c[0]), "+f"(c[1]), "+f"(c[2]), "+f"(c[3])
        : "r"(a0), "r"(a1), "r"(a2), "r"(a3), "r"(b0), "r"(b1));
}

// ===========================================================================
// conversion kernels
// ===========================================================================
__global__ void conv_q(const float* __restrict__ query, const float* __restrict__ qpos,
                       float* __restrict__ q, int n4)
{
    const int i = blockIdx.x * blockDim.x + threadIdx.x;
    if (i >= n4) return;
    float4 v = ((const float4*)query)[i];
    float4 u = ((const float4*)qpos)[i];
    v.x += u.x; v.y += u.y; v.z += u.z; v.w += u.w;
    ((float4*)q)[i] = v;
}

// Weight transposes (fp32), one launch; W_off and W_attn concatenated row-wise.
__global__ void conv_w_t_all(const float* __restrict__ Wv,
                             const float* __restrict__ Wo,
                             const float* __restrict__ Wa,
                             float* __restrict__ vt, float* __restrict__ qt)
{
    const float* W;
    float* T;
    int N;
    if (blockIdx.z == 0)      { W = Wv; T = vt;            N = 256; }
    else if (blockIdx.z == 1) { W = Wo; T = qt;            N = 256; }
    else                      { W = Wa; T = qt + 256*256;  N = 128; }
    if ((int)(blockIdx.x * 32) >= N) return;

    __shared__ float t[32][33];
    const int k0 = blockIdx.y * 32, n0 = blockIdx.x * 32;
    const int tx = threadIdx.x & 31, ty = threadIdx.x >> 5;
#pragma unroll
    for (int j = 0; j < 4; j++)
        t[ty + j * 8][tx] = W[(size_t)(k0 + ty + j * 8) * N + n0 + tx];
    __syncthreads();
#pragma unroll
    for (int j = 0; j < 4; j++) {
        const int n = n0 + ty + j * 8;
        const int k = k0 + tx;
        T[(size_t)n * 256 + k] = t[tx][ty + j * 8];
    }
}

// ===========================================================================
// tf32 1-term mma.sync GEMM with cp.async double buffering.
// C[M,N] = A @ B^T + bias, A [m][k] fp32, B [n][k] fp32 (pre-transposed), K=256.
// Block 128x128, 8 warps (2m x 4n), warp tile 64x32, BK=32 chunks.
// SMEM tiles fp32 with 36-float row stride -> conflict-free frag lds
// (bank = 4g + t mod 32 covers all 32). cvt.rna on frags in-kernel.
// mode 1: fp16 padded-row-major value output. mode 2: split off/attn epilogue.
// ===========================================================================
#define FSTR 36                                 // floats per SMEM row
#define ATILE_B (128 * FSTR * 4)                // 18432 B per tile
#define STAGE_B (2 * ATILE_B)                   // A + B per stage
#define SMEM_TOT (2 * STAGE_B)                  // 73728 B

__device__ __forceinline__ void load_chunk(uint32_t sb,
                                           const float* __restrict__ A,
                                           const float* __restrict__ B,
                                           int m0, int n0, int M, int k0, int tid)
{
#pragma unroll
    for (int i = 0; i < 4; i++) {
        const int idx = tid + i * 256;
        const int row = idx >> 3;
        const int seg = idx & 7;
        int gm = m0 + row;
        if (gm >= M) gm = M - 1;
        const uint32_t doff = (uint32_t)(row * (FSTR * 4) + seg * 16);
        CP16(sb + doff,           A + (size_t)gm * 256 + k0 + seg * 4);
        CP16(sb + ATILE_B + doff, B + (size_t)(n0 + row) * 256 + k0 + seg * 4);
    }
}

__global__ __launch_bounds__(256)
void tf32_gemm(const float* __restrict__ A, const float* __restrict__ B,
               const float* __restrict__ bias, const float* __restrict__ bias2,
               __half* __restrict__ Cv,
               float* __restrict__ C, float* __restrict__ C2,
               int M, int mode)
{
    extern __shared__ char smem[];
    const uint32_t sbase = smem_u32(smem);
    const int tid = threadIdx.x;
    const int wid = tid >> 5;
    const int lane = tid & 31;
    const int m0 = blockIdx.y * 128;
    const int n0 = blockIdx.x * 128;

    const int wm = wid >> 2;         // 0..1
    const int wn = wid & 3;          // 0..3
    const int g = lane >> 2;         // 0..7
    const int t = lane & 3;          // 0..3

    float acc[4][4][4];
#pragma unroll
    for (int i = 0; i < 4; i++)
#pragma unroll
        for (int j = 0; j < 4; j++)
#pragma unroll
            for (int r = 0; r < 4; r++) acc[i][j][r] = 0.f;

    load_chunk(sbase, A, B, m0, n0, M, 0, tid);
    CP_COMMIT();

    const int NCH = 256 / 32;
#pragma unroll 1
    for (int c = 0; c < NCH; c++) {
        if (c + 1 < NCH) {
            load_chunk(sbase + ((c + 1) & 1) * STAGE_B, A, B, m0, n0, M,
                       (c + 1) * 32, tid);
            CP_COMMIT();
            CP_WAIT(1);
        } else {
            CP_WAIT(0);
        }
        __syncthreads();

        const float* sA = (const float*)(smem + (c & 1) * STAGE_B);
        const float* sB = sA + 128 * FSTR;

#pragma unroll
        for (int ks = 0; ks < 4; ks++) {
            const int kk = ks * 8;
            uint32_t a[4][4], b[4][2];
#pragma unroll
            for (int tm = 0; tm < 4; tm++) {
                const int r = wm * 64 + tm * 16;
                a[tm][0] = f2tf(sA[(r + g)     * FSTR + kk + t]);
                a[tm][1] = f2tf(sA[(r + g + 8) * FSTR + kk + t]);
                a[tm][2] = f2tf(sA[(r + g)     * FSTR + kk + t + 4]);
                a[tm][3] = f2tf(sA[(r + g + 8) * FSTR + kk + t + 4]);
            }
#pragma unroll
            for (int tn = 0; tn < 4; tn++) {
                const int n = wn * 32 + tn * 8 + g;
                b[tn][0] = f2tf(sB[n * FSTR + kk + t]);
                b[tn][1] = f2tf(sB[n * FSTR + kk + t + 4]);
            }
#pragma unroll
            for (int tm = 0; tm < 4; tm++)
#pragma unroll
                for (int tn = 0; tn < 4; tn++)
                    mma_tf32(acc[tm][tn],
                             a[tm][0], a[tm][1], a[tm][2], a[tm][3],
                             b[tn][0], b[tn][1]);
        }
        __syncthreads();
    }

    // epilogue: c0,c1 at (row g, cols 2t..2t+1); c2,c3 at row g+8
#pragma unroll
    for (int tm = 0; tm < 4; tm++) {
#pragma unroll
        for (int half = 0; half < 2; half++) {
            const int gm = m0 + wm * 64 + tm * 16 + g + half * 8;
            if (gm >= M) continue;
#pragma unroll
            for (int tn = 0; tn < 4; tn++) {
                const int gn = n0 + wn * 32 + tn * 8 + t * 2;
                float2 o;
                o.x = acc[tm][tn][half * 2 + 0];
                o.y = acc[tm][tn][half * 2 + 1];
                if (mode == 1) {
                    float2 bsv = *(const float2*)(bias + gn);
                    o.x += bsv.x; o.y += bsv.y;
                    __half2 hv = __floats2half2_rn(o.x, o.y);
                    *(__half2*)(Cv + (size_t)gm * VSTR + gn) = hv;
                } else {
                    if (gn < 256) {
                        float2 bsv = *(const float2*)(bias + gn);
                        o.x += bsv.x; o.y += bsv.y;
                        *(float2*)(C + (size_t)gm * 256 + gn) = o;
                    } else {
                        float2 bsv = *(const float2*)(bias2 + gn - 256);
                        o.x += bsv.x; o.y += bsv.y;
                        *(float2*)(C2 + (size_t)gm * 128 + gn - 256) = o;
                    }
                }
            }
        }
    }
}

// ---------------------------------------------------------------------------
// Deformable sampling v7 (unchanged): one warp = one (b, q), all 8 heads,
// fp16 value in padded row-major layout (VSTR=320).
// ---------------------------------------------------------------------------
__global__ void sample_kernel(const float* __restrict__ refpts,
                              float* __restrict__ out)
{
    const int gwarp = (blockIdx.x * blockDim.x + threadIdx.x) >> 5;
    const int lane = threadIdx.x & 31;
    if (gwarp >= BS * NQ) return;

    const int bq = gwarp;
    const int b  = bq / NQ;
    const int h  = lane >> 2;
    const int pt = lane & 3;
    const unsigned FULL = 0xFFFFFFFFu;

    float a[4];
#pragma unroll
    for (int lv = 0; lv < 4; lv++)
        a[lv] = g_attn[(size_t)bq * 128 + h * 16 + lv * 4 + pt];

    float amax = fmaxf(fmaxf(a[0], a[1]), fmaxf(a[2], a[3]));
    amax = fmaxf(amax, __shfl_xor_sync(FULL, amax, 1));
    amax = fmaxf(amax, __shfl_xor_sync(FULL, amax, 2));
    float wgt[4];
    float es = 0.f;
#pragma unroll
    for (int lv = 0; lv < 4; lv++) { wgt[lv] = __expf(a[lv] - amax); es += wgt[lv]; }
    es += __shfl_xor_sync(FULL, es, 1);
    es += __shfl_xor_sync(FULL, es, 2);
    const float inv = 1.f / es;
#pragma unroll
    for (int lv = 0; lv < 4; lv++) wgt[lv] *= inv;

    const float LW[4] = {160.f, 80.f, 40.f, 20.f};
    const float LH[4] = {92.f, 46.f, 23.f, 12.f};
    const float rx = refpts[(size_t)bq * 8 + pt * 2 + 0];
    const float ry = refpts[(size_t)bq * 8 + pt * 2 + 1];
    float x[4], y[4];
#pragma unroll
    for (int lv = 0; lv < 4; lv++) {
        const float offx = g_off[(size_t)bq * 256 + h * 32 + lv * 8 + pt * 2 + 0];
        const float offy = g_off[(size_t)bq * 256 + h * 32 + lv * 8 + pt * 2 + 1];
        x[lv] = fmaf(rx + offx / LW[lv], LW[lv], -0.5f);
        y[lv] = fmaf(ry + offy / LH[lv], LH[lv], -0.5f);
    }

    const int HH[4] = {92, 46, 23, 12};
    const int WW[4] = {160, 80, 40, 20};
    const int ST[4] = {0, 14720, 18400, 19320};

    const uint4* __restrict__ vp =
        (const uint4*)g_vs + (size_t)b * NV * (VSTR / 8) + lane;

    float2 a0 = {0.f, 0.f}, a1 = {0.f, 0.f}, a2 = {0.f, 0.f}, a3 = {0.f, 0.f};
    const int src_base = lane & 28;

#pragma unroll
    for (int p = 0; p < 16; p++) {
        const int lv = p >> 2;
        const int pp = p & 3;
        const int src = src_base | pp;
        const float xp = __shfl_sync(FULL, x[lv], src);
        const float yp = __shfl_sync(FULL, y[lv], src);
        const float wp = __shfl_sync(FULL, wgt[lv], src);
        const int Hl = HH[lv], Wl = WW[lv], base = ST[lv];

        const float x0f = floorf(xp), y0f = floorf(yp);
        const float wx1r = xp - x0f;
        const float wy1r = yp - y0f;
        const int x0 = (int)x0f, y0 = (int)y0f;

        const bool vx0 = (unsigned)x0 < (unsigned)Wl;
        const bool vx1 = (unsigned)(x0 + 1) < (unsigned)Wl;
        const bool vy0 = (unsigned)y0 < (unsigned)Hl;
        const bool vy1 = (unsigned)(y0 + 1) < (unsigned)Hl;

        const float wy0 = vy0 ? (1.f - wy1r) * wp : 0.f;
        const float wy1 = vy1 ? wy1r * wp : 0.f;
        const float wxa = vx0 ? (1.f - wx1r) : 0.f;
        const float wxb = vx1 ? wx1r : 0.f;

        const int x0c = min(max(x0, 0), Wl - 1);
        const int x1c = min(max(x0 + 1, 0), Wl - 1);
        const int y0c = min(max(y0, 0), Hl - 1);
        const int y1c = min(max(y0 + 1, 0), Hl - 1);

        const int r0 = (base + y0c * Wl) * (VSTR / 8);
        const int r1 = (base + y1c * Wl) * (VSTR / 8);

#pragma unroll
        for (int cn = 0; cn < 4; cn++) {
            const int idx = (cn < 2 ? r0 : r1) + ((cn & 1) ? x1c : x0c) * (VSTR / 8);
            const float cw = (cn == 0 ? wy0 * wxa : cn == 1 ? wy0 * wxb
                              : cn == 2 ? wy1 * wxa : wy1 * wxb);
            const uint4 u = __ldg(vp + idx);
            const float2 f0 = __half22float2(*(const __half2*)&u.x);
            const float2 f1 = __half22float2(*(const __half2*)&u.y);
            const float2 f2 = __half22float2(*(const __half2*)&u.z);
            const float2 f3 = __half22float2(*(const __half2*)&u.w);
            a0.x = fmaf(f0.x, cw, a0.x); a0.y = fmaf(f0.y, cw, a0.y);
            a1.x = fmaf(f1.x, cw, a1.x); a1.y = fmaf(f1.y, cw, a1.y);
            a2.x = fmaf(f2.x, cw, a2.x); a2.y = fmaf(f2.y, cw, a2.y);
            a3.x = fmaf(f3.x, cw, a3.x); a3.y = fmaf(f3.y, cw, a3.y);
        }
    }

    float* op = out + (size_t)bq * EMBED + lane * 8;
    *(float4*)(op)     = make_float4(a0.x, a0.y, a1.x, a1.y);
    *(float4*)(op + 4) = make_float4(a2.x, a2.y, a3.x, a3.y);
}

// ---------------------------------------------------------------------------
extern "C" void kernel_launch(void* const* d_in, const int* in_sizes, int n_in,
                              void* d_out, int out_size)
{
    const float* query   = (const float*)d_in[0];
    const float* value   = (const float*)d_in[1];
    const float* qpos    = (const float*)d_in[2];
    const float* refpts  = (const float*)d_in[3];
    const float* W_val   = (const float*)d_in[4];
    const float* b_val   = (const float*)d_in[5];
    const float* W_off   = (const float*)d_in[6];
    const float* b_off   = (const float*)d_in[7];
    const float* W_attn  = (const float*)d_in[8];
    const float* b_attn  = (const float*)d_in[9];
    float* out = (float*)d_out;

    __half* pvs;
    float *poff, *pattn, *pq, *pwvt, *pwqt;
    cudaGetSymbolAddress((void**)&pvs, g_vs);
    cudaGetSymbolAddress((void**)&poff, g_off);
    cudaGetSymbolAddress((void**)&pattn, g_attn);
    cudaGetSymbolAddress((void**)&pq, g_q);
    cudaGetSymbolAddress((void**)&pwvt, g_wvt);
    cudaGetSymbolAddress((void**)&pwqt, g_wqt);

    const int Mv = BS * NV;      // 39120
    const int Mq = BS * NQ;      // 20000

    cudaFuncSetAttribute(tf32_gemm, cudaFuncAttributeMaxDynamicSharedMemorySize,
                         SMEM_TOT);

    // q = query + qpos; weight transposes
    {
        int n4 = Mq * 256 / 4;
        conv_q<<<(n4 + 255) / 256, 256>>>(query, qpos, pq, n4);
    }
    conv_w_t_all<<<dim3(8, 8, 3), 256>>>(W_val, W_off, W_attn, pwvt, pwqt);

    // value projection -> fp16 padded row-major (A = value directly)
    tf32_gemm<<<dim3(2, (Mv + 127) / 128), 256, SMEM_TOT>>>(
        value, pwvt, b_val, nullptr, pvs, nullptr, nullptr, Mv, 1);
    // merged offsets + attn logits: N = 384
    tf32_gemm<<<dim3(3, (Mq + 127) / 128), 256, SMEM_TOT>>>(
        pq, pwqt, b_off, b_attn, nullptr, poff, pattn, Mq, 2);

    // sampling + weighted sum (one warp per (b,q))
    {
        const int total_warps = BS * NQ;                 // 20000
        const int warps_per_block = 8;
        const int blocks = (total_warps + warps_per_block - 1) / warps_per_block;
        sample_kernel<<<blocks, warps_per_block * 32>>>(refpts, out);
    }
}